// round 3
// baseline (speedup 1.0000x reference)
#include <cuda_runtime.h>

// ---------------------------------------------------------------------------
// GATv2 forward: xl=x@Wl, xr=x@Wr; per-edge leaky-relu attention logits;
// segment softmax over dst; weighted scatter-sum; bias+relu; per-graph max
// pool (batch_ids sorted); final MLP + relu.
// Shapes (fixed by problem): N=50000, E=800000, D=128, H=4, C=32, HC=128, G=64
// edge_index / batch_ids delivered as int32 by the harness (int64 canonicalized).
// ---------------------------------------------------------------------------

#define NMAX   50048
#define EMAX   800000
#define ETOTMAX (EMAX + NMAX)
#define GMAX   256

__device__ float    g_xl[(size_t)NMAX * 128];
__device__ float    g_xr[(size_t)NMAX * 128];
__device__ float    g_out[(size_t)NMAX * 128];
__device__ float    g_logit[(size_t)ETOTMAX * 4];
__device__ unsigned g_mkey[NMAX * 4];
__device__ float    g_denom[NMAX * 4];
__device__ float    g_pooled[GMAX * 128];

__device__ __forceinline__ int clampi(int v, int lo, int hi) {
    return v < lo ? lo : (v > hi ? hi : v);
}

// order-preserving float -> uint key (monotone for all finite floats)
__device__ __forceinline__ unsigned f2key(float f) {
    unsigned u = __float_as_uint(f);
    return (u & 0x80000000u) ? ~u : (u | 0x80000000u);
}
__device__ __forceinline__ float key2f(unsigned k) {
    unsigned u = (k & 0x80000000u) ? (k & 0x7FFFFFFFu) : ~k;
    return __uint_as_float(u);
}

// ---------------------------------------------------------------------------
__global__ void init_kernel(int n_out_elems, int n_node4, int n_pool) {
    int i = blockIdx.x * blockDim.x + threadIdx.x;
    int stride = gridDim.x * blockDim.x;
    for (int idx = i; idx < n_out_elems; idx += stride) g_out[idx] = 0.f;
    for (int idx = i; idx < n_node4; idx += stride) { g_mkey[idx] = 0u; g_denom[idx] = 0.f; }
    for (int idx = i; idx < n_pool; idx += stride) g_pooled[idx] = 0.f;
}

// ---------------------------------------------------------------------------
// Tiled fp32 GEMM: 64x64 output tile of (x @ W), K=128 split into 2 K-tiles
// of 64 so static smem = 32KB. cb 0,1 -> Wl -> g_xl ; cb 2,3 -> Wr -> g_xr.
// ---------------------------------------------------------------------------
__global__ void __launch_bounds__(256) gemm_kernel(
    const float* __restrict__ x,
    const float* __restrict__ Wl,
    const float* __restrict__ Wr,
    int N)
{
    __shared__ float As[64][64];   // 16 KB
    __shared__ float Bs[64][64];   // 16 KB

    int cb   = blockIdx.x;              // 0..3
    int row0 = blockIdx.y * 64;
    const float* W   = (cb < 2) ? Wl : Wr;
    float*       dst = (cb < 2) ? g_xl : g_xr;
    int col0 = (cb & 1) * 64;
    int t = threadIdx.x;
    int tx = t & 15, ty = t >> 4;

    float acc[4][4] = {};

#pragma unroll
    for (int k0 = 0; k0 < 128; k0 += 64) {
#pragma unroll
        for (int i = 0; i < 4; i++) {
            int idx = t + i * 256;          // 0..1023
            int r = idx >> 4, c4 = idx & 15;
            float4 v = make_float4(0.f, 0.f, 0.f, 0.f);
            if (row0 + r < N)
                v = *(const float4*)&x[(size_t)(row0 + r) * 128 + k0 + c4 * 4];
            *(float4*)&As[r][c4 * 4] = v;
        }
#pragma unroll
        for (int i = 0; i < 4; i++) {
            int idx = t + i * 256;
            int k = idx >> 4, j4 = idx & 15;
            *(float4*)&Bs[k][j4 * 4] = *(const float4*)&W[(k0 + k) * 128 + col0 + j4 * 4];
        }
        __syncthreads();

#pragma unroll 8
        for (int k = 0; k < 64; k++) {
            float a0 = As[ty * 4 + 0][k];
            float a1 = As[ty * 4 + 1][k];
            float a2 = As[ty * 4 + 2][k];
            float a3 = As[ty * 4 + 3][k];
            float4 b = *(float4*)&Bs[k][tx * 4];
            acc[0][0] += a0 * b.x; acc[0][1] += a0 * b.y; acc[0][2] += a0 * b.z; acc[0][3] += a0 * b.w;
            acc[1][0] += a1 * b.x; acc[1][1] += a1 * b.y; acc[1][2] += a1 * b.z; acc[1][3] += a1 * b.w;
            acc[2][0] += a2 * b.x; acc[2][1] += a2 * b.y; acc[2][2] += a2 * b.z; acc[2][3] += a2 * b.w;
            acc[3][0] += a3 * b.x; acc[3][1] += a3 * b.y; acc[3][2] += a3 * b.z; acc[3][3] += a3 * b.w;
        }
        __syncthreads();
    }

#pragma unroll
    for (int i = 0; i < 4; i++) {
        int row = row0 + ty * 4 + i;
        if (row < N) {
            float4 v = make_float4(acc[i][0], acc[i][1], acc[i][2], acc[i][3]);
            *(float4*)&dst[(size_t)row * 128 + col0 + tx * 4] = v;
        }
    }
}

// ---------------------------------------------------------------------------
// Warp per edge: logits[e,h] = sum_c att[h,c]*leaky_relu(xl[s,h,c]+xr[d,h,c]),
// atomicMax into per-(dst,head) max key. Edges [E, E+N) are self loops.
// ---------------------------------------------------------------------------
__global__ void __launch_bounds__(256) logits_kernel(
    const int* __restrict__ ei,
    const float* __restrict__ att,
    int E, int Etot, int N)
{
    int warp = (blockIdx.x * 256 + threadIdx.x) >> 5;
    int lane = threadIdx.x & 31;
    if (warp >= Etot) return;
    int s, d;
    if (warp < E) { s = clampi(ei[warp], 0, N - 1); d = clampi(ei[E + warp], 0, N - 1); }
    else          { s = warp - E; d = s; }

    float4 a = *(const float4*)&g_xl[(size_t)s * 128 + lane * 4];
    float4 b = *(const float4*)&g_xr[(size_t)d * 128 + lane * 4];
    float4 w = *(const float4*)&att[lane * 4];

    float vx = a.x + b.x; vx = vx > 0.f ? vx : 0.2f * vx;
    float vy = a.y + b.y; vy = vy > 0.f ? vy : 0.2f * vy;
    float vz = a.z + b.z; vz = vz > 0.f ? vz : 0.2f * vz;
    float vw = a.w + b.w; vw = vw > 0.f ? vw : 0.2f * vw;
    float partial = vx * w.x + vy * w.y + vz * w.z + vw * w.w;

    // reduce within each 8-lane head group
    partial += __shfl_xor_sync(0xFFFFFFFFu, partial, 1);
    partial += __shfl_xor_sync(0xFFFFFFFFu, partial, 2);
    partial += __shfl_xor_sync(0xFFFFFFFFu, partial, 4);

    if ((lane & 7) == 0) {
        int h = lane >> 3;
        g_logit[(size_t)warp * 4 + h] = partial;
        atomicMax(&g_mkey[d * 4 + h], f2key(partial));
    }
}

// ---------------------------------------------------------------------------
// One thread per (edge, head): ex = exp(logit - m[dst]); atomicAdd denom.
// ---------------------------------------------------------------------------
__global__ void __launch_bounds__(256) exp_kernel(
    const int* __restrict__ ei, int E, int Etot, int N)
{
    int tid = blockIdx.x * 256 + threadIdx.x;
    if (tid >= Etot * 4) return;
    int e = tid >> 2, h = tid & 3;
    int d = (e < E) ? clampi(ei[E + e], 0, N - 1) : (e - E);
    float m = key2f(g_mkey[d * 4 + h]);
    float ex = __expf(g_logit[tid] - m);
    g_logit[tid] = ex;
    atomicAdd(&g_denom[d * 4 + h], ex);
}

// ---------------------------------------------------------------------------
// Warp per edge: out[dst] += alpha * xl[src], vector float4 atomics.
// ---------------------------------------------------------------------------
__global__ void __launch_bounds__(256) scatter_kernel(
    const int* __restrict__ ei, int E, int Etot, int N)
{
    int warp = (blockIdx.x * 256 + threadIdx.x) >> 5;
    int lane = threadIdx.x & 31;
    if (warp >= Etot) return;
    int s, d;
    if (warp < E) { s = clampi(ei[warp], 0, N - 1); d = clampi(ei[E + warp], 0, N - 1); }
    else          { s = warp - E; d = s; }

    int h = lane >> 3;
    float alpha = g_logit[(size_t)warp * 4 + h] / g_denom[d * 4 + h];
    float4 xv = *(const float4*)&g_xl[(size_t)s * 128 + lane * 4];
    xv.x *= alpha; xv.y *= alpha; xv.z *= alpha; xv.w *= alpha;
    atomicAdd((float4*)&g_out[(size_t)d * 128 + lane * 4], xv);
}

// ---------------------------------------------------------------------------
// Per-graph max pool. batch_ids is SORTED: per-thread running max over 64
// consecutive nodes with flush-on-graph-change. relu -> values >= 0 so
// int-punned atomicMax on floats is valid with 0-init.
// ---------------------------------------------------------------------------
__global__ void __launch_bounds__(128) pool_kernel(
    const int* __restrict__ batch,
    const float* __restrict__ bias, int N)
{
    int j  = threadIdx.x;          // 0..127
    int n0 = blockIdx.x * 64;
    float bj = bias[j];
    int curg = -1;
    float curmax = 0.f;
    for (int i = 0; i < 64; i++) {
        int n = n0 + i;
        if (n >= N) break;
        int g = clampi(batch[n], 0, GMAX - 1);
        if (g != curg) {
            if (curg >= 0)
                atomicMax((int*)&g_pooled[curg * 128 + j], __float_as_int(curmax));
            curg = g; curmax = 0.f;
        }
        float v = g_out[(size_t)n * 128 + j] + bj;
        v = fmaxf(v, 0.f);
        curmax = fmaxf(curmax, v);
    }
    if (curg >= 0)
        atomicMax((int*)&g_pooled[curg * 128 + j], __float_as_int(curmax));
}

// ---------------------------------------------------------------------------
// Final MLP: out[g,:] = relu(pooled[g,:] @ W_mlp + b_mlp). One block per graph.
// ---------------------------------------------------------------------------
__global__ void __launch_bounds__(128) mlp_kernel(
    const float* __restrict__ W,
    const float* __restrict__ b,
    float* __restrict__ out)
{
    __shared__ float p[128];
    int j = threadIdx.x, g = blockIdx.x;
    p[j] = g_pooled[g * 128 + j];
    __syncthreads();
    float acc = b[j];
#pragma unroll 8
    for (int k = 0; k < 128; k++)
        acc += p[k] * W[k * 128 + j];
    out[g * 128 + j] = fmaxf(acc, 0.f);
}

// ---------------------------------------------------------------------------
extern "C" void kernel_launch(void* const* d_in, const int* in_sizes, int n_in,
                              void* d_out, int out_size)
{
    const float* x     = (const float*)d_in[0];
    const int*   ei    = (const int*)d_in[1];     // int64 canonicalized to int32
    const int*   batch = (const int*)d_in[2];     // int64 canonicalized to int32
    // num_graphs (python int) may arrive as a 1-element buffer
    int base = (n_in >= 10) ? 4 : 3;
    const float* Wl   = (const float*)d_in[base + 0];
    const float* Wr   = (const float*)d_in[base + 1];
    const float* att  = (const float*)d_in[base + 2];
    const float* bias = (const float*)d_in[base + 3];
    const float* Wm   = (const float*)d_in[base + 4];
    const float* bm   = (const float*)d_in[base + 5];

    int N = in_sizes[0] / 128;
    int E = in_sizes[1] / 2;
    int G = out_size / 128;
    int Etot = E + N;
    float* out = (float*)d_out;

    init_kernel<<<(N * 128 + 255) / 256, 256>>>(N * 128, N * 4, G * 128);

    dim3 ggrid(4, (N + 63) / 64);
    gemm_kernel<<<ggrid, 256>>>(x, Wl, Wr, N);

    int eblocks = (Etot * 32 + 255) / 256;
    logits_kernel<<<eblocks, 256>>>(ei, att, E, Etot, N);
    exp_kernel<<<(Etot * 4 + 255) / 256, 256>>>(ei, E, Etot, N);
    scatter_kernel<<<eblocks, 256>>>(ei, E, Etot, N);

    pool_kernel<<<(N + 63) / 64, 128>>>(batch, bias, N);
    mlp_kernel<<<G, 128>>>(Wm, bm, out);
}

// round 4
// speedup vs baseline: 1.1810x; 1.1810x over previous
#include <cuda_runtime.h>

// ---------------------------------------------------------------------------
// GATv2 forward, CSR-restructured:
//   xl=x@Wl, xr=x@Wr (tiled fp32 GEMM)
//   CSR build over dst (hist -> scan -> fill)
//   aggregate: block per dst node; warp h = head h; softmax WITHOUT max-shift
//   (logits ~N(0,1), exp safe in fp32; max cancels in alpha exactly);
//   single gather of xl[src] feeds both logit and weighted sum; result fused
//   with bias+relu and atomicMax'ed directly into the per-graph pool.
//   mlp: pooled @ W_mlp + b, relu.
// Shapes: N=50000, E=800000, D=128, H=4, C=32, HC=128, G=64.
// edge_index / batch_ids arrive as int32 (harness canonicalizes int64).
// ---------------------------------------------------------------------------

#define NMAX   50048
#define EMAX   800000
#define GMAX   256

__device__ float g_xl[(size_t)NMAX * 128];
__device__ float g_xr[(size_t)NMAX * 128];
__device__ int   g_cnt[NMAX];
__device__ int   g_rowptr[NMAX + 1];
__device__ int   g_cursor[NMAX];
__device__ int   g_csrc[EMAX];
__device__ float g_pooled[GMAX * 128];

__device__ __forceinline__ int clampi(int v, int lo, int hi) {
    return v < lo ? lo : (v > hi ? hi : v);
}

// ---------------------------------------------------------------------------
__global__ void init_kernel(int n_nodes, int n_pool) {
    int i = blockIdx.x * blockDim.x + threadIdx.x;
    int stride = gridDim.x * blockDim.x;
    for (int idx = i; idx < n_nodes; idx += stride) g_cnt[idx] = 0;
    for (int idx = i; idx < n_pool; idx += stride) g_pooled[idx] = 0.f;
}

// ---------------------------------------------------------------------------
// Tiled fp32 GEMM: 64x64 output tile of (x @ W), K=128 in 2 K-tiles of 64.
// cb 0,1 -> Wl -> g_xl ; cb 2,3 -> Wr -> g_xr.
// ---------------------------------------------------------------------------
__global__ void __launch_bounds__(256) gemm_kernel(
    const float* __restrict__ x,
    const float* __restrict__ Wl,
    const float* __restrict__ Wr,
    int N)
{
    __shared__ float As[64][64];
    __shared__ float Bs[64][64];

    int cb   = blockIdx.x;
    int row0 = blockIdx.y * 64;
    const float* W   = (cb < 2) ? Wl : Wr;
    float*       dst = (cb < 2) ? g_xl : g_xr;
    int col0 = (cb & 1) * 64;
    int t = threadIdx.x;
    int tx = t & 15, ty = t >> 4;

    float acc[4][4] = {};

#pragma unroll
    for (int k0 = 0; k0 < 128; k0 += 64) {
#pragma unroll
        for (int i = 0; i < 4; i++) {
            int idx = t + i * 256;
            int r = idx >> 4, c4 = idx & 15;
            float4 v = make_float4(0.f, 0.f, 0.f, 0.f);
            if (row0 + r < N)
                v = *(const float4*)&x[(size_t)(row0 + r) * 128 + k0 + c4 * 4];
            *(float4*)&As[r][c4 * 4] = v;
        }
#pragma unroll
        for (int i = 0; i < 4; i++) {
            int idx = t + i * 256;
            int k = idx >> 4, j4 = idx & 15;
            *(float4*)&Bs[k][j4 * 4] = *(const float4*)&W[(k0 + k) * 128 + col0 + j4 * 4];
        }
        __syncthreads();

#pragma unroll 8
        for (int k = 0; k < 64; k++) {
            float a0 = As[ty * 4 + 0][k];
            float a1 = As[ty * 4 + 1][k];
            float a2 = As[ty * 4 + 2][k];
            float a3 = As[ty * 4 + 3][k];
            float4 b = *(float4*)&Bs[k][tx * 4];
            acc[0][0] += a0 * b.x; acc[0][1] += a0 * b.y; acc[0][2] += a0 * b.z; acc[0][3] += a0 * b.w;
            acc[1][0] += a1 * b.x; acc[1][1] += a1 * b.y; acc[1][2] += a1 * b.z; acc[1][3] += a1 * b.w;
            acc[2][0] += a2 * b.x; acc[2][1] += a2 * b.y; acc[2][2] += a2 * b.z; acc[2][3] += a2 * b.w;
            acc[3][0] += a3 * b.x; acc[3][1] += a3 * b.y; acc[3][2] += a3 * b.z; acc[3][3] += a3 * b.w;
        }
        __syncthreads();
    }

#pragma unroll
    for (int i = 0; i < 4; i++) {
        int row = row0 + ty * 4 + i;
        if (row < N) {
            float4 v = make_float4(acc[i][0], acc[i][1], acc[i][2], acc[i][3]);
            *(float4*)&dst[(size_t)row * 128 + col0 + tx * 4] = v;
        }
    }
}

// ---------------------------------------------------------------------------
// CSR build: histogram of dst, exclusive scan, fill src lists.
// ---------------------------------------------------------------------------
__global__ void hist_kernel(const int* __restrict__ ei, int E, int N) {
    int i = blockIdx.x * blockDim.x + threadIdx.x;
    int stride = gridDim.x * blockDim.x;
    for (int e = i; e < E; e += stride)
        atomicAdd(&g_cnt[clampi(ei[E + e], 0, N - 1)], 1);
}

// single-block exclusive scan over g_cnt[0..N) -> g_rowptr/g_cursor
__global__ void __launch_bounds__(1024) scan_kernel(int N) {
    __shared__ int s[1024];
    int t = threadIdx.x;
    int running = 0;
    for (int base = 0; base < N; base += 1024) {
        int v = (base + t < N) ? g_cnt[base + t] : 0;
        s[t] = v;
        __syncthreads();
#pragma unroll
        for (int off = 1; off < 1024; off <<= 1) {
            int add = (t >= off) ? s[t - off] : 0;
            __syncthreads();
            s[t] += add;
            __syncthreads();
        }
        int excl = running + s[t] - v;
        if (base + t < N) { g_rowptr[base + t] = excl; g_cursor[base + t] = excl; }
        int tot = s[1023];
        __syncthreads();
        running += tot;
    }
    if (t == 0) g_rowptr[N] = running;
}

__global__ void fill_kernel(const int* __restrict__ ei, int E, int N) {
    int i = blockIdx.x * blockDim.x + threadIdx.x;
    int stride = gridDim.x * blockDim.x;
    for (int e = i; e < E; e += stride) {
        int d = clampi(ei[E + e], 0, N - 1);
        int pos = atomicAdd(&g_cursor[d], 1);
        g_csrc[pos] = clampi(ei[e], 0, N - 1);
    }
}

// ---------------------------------------------------------------------------
// Aggregate: one block (128 thr = 4 warps) per dst node. Warp h owns head h;
// thread j = h*32+c owns channel c. For each incoming edge (self-loop first):
//   t_j = att[j] * leaky_relu(xl[src][j] + xr[d][j])
//   logit = butterfly-reduce over the warp (all lanes get it)
//   ex = expf(logit)  [no max-shift: logits are O(1), cancels in alpha]
//   denom += ex ; acc_j += ex * xl[src][j]
// Then out_j = relu(acc_j/denom + bias_j), atomicMax into pooled[batch[d]].
// ---------------------------------------------------------------------------
__device__ __forceinline__ float warp_sum(float v) {
    v += __shfl_xor_sync(0xFFFFFFFFu, v, 16);
    v += __shfl_xor_sync(0xFFFFFFFFu, v, 8);
    v += __shfl_xor_sync(0xFFFFFFFFu, v, 4);
    v += __shfl_xor_sync(0xFFFFFFFFu, v, 2);
    v += __shfl_xor_sync(0xFFFFFFFFu, v, 1);
    return v;
}

__global__ void __launch_bounds__(128) aggregate_kernel(
    const float* __restrict__ att,
    const float* __restrict__ bias,
    const int* __restrict__ batch,
    int N)
{
    int d = blockIdx.x;
    if (d >= N) return;
    int j = threadIdx.x;

    float xr_v  = g_xr[(size_t)d * 128 + j];
    float att_v = att[j];

    // self loop
    float xs = g_xl[(size_t)d * 128 + j];
    float v  = xs + xr_v;
    v = v > 0.f ? v : 0.2f * v;
    float logit = warp_sum(v * att_v);
    float ex    = __expf(logit);
    float denom = ex;
    float acc   = ex * xs;

    int p    = g_rowptr[d];
    int pend = g_rowptr[d + 1];

    for (; p + 1 < pend; p += 2) {
        int s0 = g_csrc[p], s1 = g_csrc[p + 1];
        float x0 = g_xl[(size_t)s0 * 128 + j];
        float x1 = g_xl[(size_t)s1 * 128 + j];
        float v0 = x0 + xr_v; v0 = v0 > 0.f ? v0 : 0.2f * v0;
        float v1 = x1 + xr_v; v1 = v1 > 0.f ? v1 : 0.2f * v1;
        float t0 = v0 * att_v, t1 = v1 * att_v;
#pragma unroll
        for (int m = 16; m >= 1; m >>= 1) {
            t0 += __shfl_xor_sync(0xFFFFFFFFu, t0, m);
            t1 += __shfl_xor_sync(0xFFFFFFFFu, t1, m);
        }
        float e0 = __expf(t0), e1 = __expf(t1);
        denom += e0 + e1;
        acc   += e0 * x0 + e1 * x1;
    }
    if (p < pend) {
        int s0 = g_csrc[p];
        float x0 = g_xl[(size_t)s0 * 128 + j];
        float v0 = x0 + xr_v; v0 = v0 > 0.f ? v0 : 0.2f * v0;
        float t0 = warp_sum(v0 * att_v);
        float e0 = __expf(t0);
        denom += e0;
        acc   += e0 * x0;
    }

    float o = fmaxf(acc / denom + bias[j], 0.f);
    int g = clampi(batch[d], 0, GMAX - 1);
    atomicMax((int*)&g_pooled[g * 128 + j], __float_as_int(o));
}

// ---------------------------------------------------------------------------
// Final MLP: out[g,:] = relu(pooled[g,:] @ W_mlp + b_mlp). One block per graph.
// ---------------------------------------------------------------------------
__global__ void __launch_bounds__(128) mlp_kernel(
    const float* __restrict__ W,
    const float* __restrict__ b,
    float* __restrict__ out)
{
    __shared__ float pbuf[128];
    int j = threadIdx.x, g = blockIdx.x;
    pbuf[j] = g_pooled[g * 128 + j];
    __syncthreads();
    float acc = b[j];
#pragma unroll 8
    for (int k = 0; k < 128; k++)
        acc += pbuf[k] * W[k * 128 + j];
    out[g * 128 + j] = fmaxf(acc, 0.f);
}

// ---------------------------------------------------------------------------
extern "C" void kernel_launch(void* const* d_in, const int* in_sizes, int n_in,
                              void* d_out, int out_size)
{
    const float* x     = (const float*)d_in[0];
    const int*   ei    = (const int*)d_in[1];
    const int*   batch = (const int*)d_in[2];
    int base = (n_in >= 10) ? 4 : 3;
    const float* Wl   = (const float*)d_in[base + 0];
    const float* Wr   = (const float*)d_in[base + 1];
    const float* att  = (const float*)d_in[base + 2];
    const float* bias = (const float*)d_in[base + 3];
    const float* Wm   = (const float*)d_in[base + 4];
    const float* bm   = (const float*)d_in[base + 5];

    int N = in_sizes[0] / 128;
    int E = in_sizes[1] / 2;
    int G = out_size / 128;
    float* out = (float*)d_out;

    init_kernel<<<(N + 255) / 256, 256>>>(N, G * 128);                 // launch 0

    dim3 ggrid(4, (N + 63) / 64);
    gemm_kernel<<<ggrid, 256>>>(x, Wl, Wr, N);                         // launch 1

    hist_kernel<<<592, 256>>>(ei, E, N);                               // launch 2
    scan_kernel<<<1, 1024>>>(N);                                       // launch 3
    fill_kernel<<<592, 256>>>(ei, E, N);                               // launch 4
    aggregate_kernel<<<N, 128>>>(att, bias, batch, N);                 // launch 5 (ncu -s 5)
    mlp_kernel<<<G, 128>>>(Wm, bm, out);                               // launch 6
}

// round 5
// speedup vs baseline: 1.4740x; 1.2481x over previous
#include <cuda_runtime.h>

// ---------------------------------------------------------------------------
// GATv2 forward, CSR-restructured, multi-block scan:
//   xl=x@Wl, xr=x@Wr (tiled fp32 GEMM)
//   CSR build over dst (hist -> 3-step scan -> fill)
//   aggregate: block per dst node; softmax without max-shift (cancels in alpha)
//   fused bias+relu+per-graph atomicMax pool; then tiny MLP.
// Shapes: N=50000, E=800000, D=128, H=4, C=32, HC=128, G=64.
// edge_index / batch_ids arrive as int32 (harness canonicalizes int64).
// ---------------------------------------------------------------------------

#define NMAX   50048
#define EMAX   800000
#define GMAX   256
#define NBLK   ((NMAX + 1023) / 1024)   // scan chunks (<= 64 required by scan2)

__device__ float g_xl[(size_t)NMAX * 128];
__device__ float g_xr[(size_t)NMAX * 128];
__device__ int   g_cnt[NMAX];
__device__ int   g_rowptr[NMAX + 1];
__device__ int   g_cursor[NMAX];
__device__ int   g_csrc[EMAX];
__device__ int   g_bsum[64];
__device__ int   g_boff[64];
__device__ float g_pooled[GMAX * 128];

__device__ __forceinline__ int clampi(int v, int lo, int hi) {
    return v < lo ? lo : (v > hi ? hi : v);
}

// ---------------------------------------------------------------------------
__global__ void init_kernel(int n_nodes, int n_pool) {
    int i = blockIdx.x * blockDim.x + threadIdx.x;
    int stride = gridDim.x * blockDim.x;
    for (int idx = i; idx < n_nodes; idx += stride) g_cnt[idx] = 0;
    for (int idx = i; idx < n_pool; idx += stride) g_pooled[idx] = 0.f;
}

// ---------------------------------------------------------------------------
// CSR build: histogram of dst.
// ---------------------------------------------------------------------------
__global__ void hist_kernel(const int* __restrict__ ei, int E, int N) {
    int i = blockIdx.x * blockDim.x + threadIdx.x;
    int stride = gridDim.x * blockDim.x;
    for (int e = i; e < E; e += stride)
        atomicAdd(&g_cnt[clampi(ei[E + e], 0, N - 1)], 1);
}

// ---------------------------------------------------------------------------
// Multi-block exclusive scan of g_cnt -> g_rowptr/g_cursor.
// scan1: per-1024-chunk block scan (warp shuffles), writes local exclusive
//        prefix into g_rowptr and the chunk total into g_bsum[blockIdx].
// ---------------------------------------------------------------------------
__global__ void __launch_bounds__(1024) scan1_kernel(int N) {
    __shared__ int wsum[32];
    int base = blockIdx.x * 1024;
    int t = threadIdx.x, lane = t & 31, w = t >> 5;
    int v = (base + t < N) ? g_cnt[base + t] : 0;

    // inclusive warp scan
    int x = v;
#pragma unroll
    for (int off = 1; off < 32; off <<= 1) {
        int y = __shfl_up_sync(0xFFFFFFFFu, x, off);
        if (lane >= off) x += y;
    }
    if (lane == 31) wsum[w] = x;
    __syncthreads();
    if (w == 0) {
        int s = wsum[lane];
#pragma unroll
        for (int off = 1; off < 32; off <<= 1) {
            int y = __shfl_up_sync(0xFFFFFFFFu, s, off);
            if (lane >= off) s += y;
        }
        wsum[lane] = s;
    }
    __syncthreads();

    int excl = x - v + (w > 0 ? wsum[w - 1] : 0);
    if (base + t < N) g_rowptr[base + t] = excl;
    if (t == 1023) g_bsum[blockIdx.x] = excl + v;
}

// scan2: exclusive scan of up to 64 block totals (one tiny block).
__global__ void __launch_bounds__(64) scan2_kernel(int nb) {
    __shared__ int s[64];
    int t = threadIdx.x;
    int v = (t < nb) ? g_bsum[t] : 0;
    s[t] = v;
    __syncthreads();
#pragma unroll
    for (int off = 1; off < 64; off <<= 1) {
        int add = (t >= off) ? s[t - off] : 0;
        __syncthreads();
        s[t] += add;
        __syncthreads();
    }
    if (t < nb) g_boff[t] = s[t] - v;
}

// scan3: add chunk offsets; materialize rowptr + cursor; rowptr[N] = E.
__global__ void __launch_bounds__(1024) scan3_kernel(int N, int E) {
    int i = blockIdx.x * 1024 + threadIdx.x;
    if (i < N) {
        int r = g_rowptr[i] + g_boff[blockIdx.x];
        g_rowptr[i] = r;
        g_cursor[i] = r;
    }
    if (i == 0) g_rowptr[N] = E;
}

// ---------------------------------------------------------------------------
// Tiled fp32 GEMM: 64x64 output tile of (x @ W), K=128 in 2 K-tiles of 64.
// cb 0,1 -> Wl -> g_xl ; cb 2,3 -> Wr -> g_xr.
// ---------------------------------------------------------------------------
__global__ void __launch_bounds__(256) gemm_kernel(
    const float* __restrict__ x,
    const float* __restrict__ Wl,
    const float* __restrict__ Wr,
    int N)
{
    __shared__ float As[64][64];
    __shared__ float Bs[64][64];

    int cb   = blockIdx.x;
    int row0 = blockIdx.y * 64;
    const float* W   = (cb < 2) ? Wl : Wr;
    float*       dst = (cb < 2) ? g_xl : g_xr;
    int col0 = (cb & 1) * 64;
    int t = threadIdx.x;
    int tx = t & 15, ty = t >> 4;

    float acc[4][4] = {};

#pragma unroll
    for (int k0 = 0; k0 < 128; k0 += 64) {
#pragma unroll
        for (int i = 0; i < 4; i++) {
            int idx = t + i * 256;
            int r = idx >> 4, c4 = idx & 15;
            float4 v = make_float4(0.f, 0.f, 0.f, 0.f);
            if (row0 + r < N)
                v = *(const float4*)&x[(size_t)(row0 + r) * 128 + k0 + c4 * 4];
            *(float4*)&As[r][c4 * 4] = v;
        }
#pragma unroll
        for (int i = 0; i < 4; i++) {
            int idx = t + i * 256;
            int k = idx >> 4, j4 = idx & 15;
            *(float4*)&Bs[k][j4 * 4] = *(const float4*)&W[(k0 + k) * 128 + col0 + j4 * 4];
        }
        __syncthreads();

#pragma unroll 8
        for (int k = 0; k < 64; k++) {
            float a0 = As[ty * 4 + 0][k];
            float a1 = As[ty * 4 + 1][k];
            float a2 = As[ty * 4 + 2][k];
            float a3 = As[ty * 4 + 3][k];
            float4 b = *(float4*)&Bs[k][tx * 4];
            acc[0][0] += a0 * b.x; acc[0][1] += a0 * b.y; acc[0][2] += a0 * b.z; acc[0][3] += a0 * b.w;
            acc[1][0] += a1 * b.x; acc[1][1] += a1 * b.y; acc[1][2] += a1 * b.z; acc[1][3] += a1 * b.w;
            acc[2][0] += a2 * b.x; acc[2][1] += a2 * b.y; acc[2][2] += a2 * b.z; acc[2][3] += a2 * b.w;
            acc[3][0] += a3 * b.x; acc[3][1] += a3 * b.y; acc[3][2] += a3 * b.z; acc[3][3] += a3 * b.w;
        }
        __syncthreads();
    }

#pragma unroll
    for (int i = 0; i < 4; i++) {
        int row = row0 + ty * 4 + i;
        if (row < N) {
            float4 v = make_float4(acc[i][0], acc[i][1], acc[i][2], acc[i][3]);
            *(float4*)&dst[(size_t)row * 128 + col0 + tx * 4] = v;
        }
    }
}

// ---------------------------------------------------------------------------
// fill: scatter src ids into CSR lists via per-dst cursors.
// ---------------------------------------------------------------------------
__global__ void fill_kernel(const int* __restrict__ ei, int E, int N) {
    int i = blockIdx.x * blockDim.x + threadIdx.x;
    int stride = gridDim.x * blockDim.x;
    for (int e = i; e < E; e += stride) {
        int d = clampi(ei[E + e], 0, N - 1);
        int pos = atomicAdd(&g_cursor[d], 1);
        g_csrc[pos] = clampi(ei[e], 0, N - 1);
    }
}

// ---------------------------------------------------------------------------
// Aggregate: one block (128 thr = 4 warps) per dst node. Warp h owns head h.
// Softmax without max-shift: logits O(1), shift cancels exactly in alpha.
// Fused bias + relu + per-graph atomicMax pooling.
// ---------------------------------------------------------------------------
__device__ __forceinline__ float warp_sum(float v) {
    v += __shfl_xor_sync(0xFFFFFFFFu, v, 16);
    v += __shfl_xor_sync(0xFFFFFFFFu, v, 8);
    v += __shfl_xor_sync(0xFFFFFFFFu, v, 4);
    v += __shfl_xor_sync(0xFFFFFFFFu, v, 2);
    v += __shfl_xor_sync(0xFFFFFFFFu, v, 1);
    return v;
}

__global__ void __launch_bounds__(128) aggregate_kernel(
    const float* __restrict__ att,
    const float* __restrict__ bias,
    const int* __restrict__ batch,
    int N)
{
    int d = blockIdx.x;
    if (d >= N) return;
    int j = threadIdx.x;

    float xr_v  = g_xr[(size_t)d * 128 + j];
    float att_v = att[j];

    // self loop
    float xs = g_xl[(size_t)d * 128 + j];
    float v  = xs + xr_v;
    v = v > 0.f ? v : 0.2f * v;
    float logit = warp_sum(v * att_v);
    float ex    = __expf(logit);
    float denom = ex;
    float acc   = ex * xs;

    int p    = g_rowptr[d];
    int pend = g_rowptr[d + 1];

    for (; p + 1 < pend; p += 2) {
        int s0 = g_csrc[p], s1 = g_csrc[p + 1];
        float x0 = g_xl[(size_t)s0 * 128 + j];
        float x1 = g_xl[(size_t)s1 * 128 + j];
        float v0 = x0 + xr_v; v0 = v0 > 0.f ? v0 : 0.2f * v0;
        float v1 = x1 + xr_v; v1 = v1 > 0.f ? v1 : 0.2f * v1;
        float t0 = v0 * att_v, t1 = v1 * att_v;
#pragma unroll
        for (int m = 16; m >= 1; m >>= 1) {
            t0 += __shfl_xor_sync(0xFFFFFFFFu, t0, m);
            t1 += __shfl_xor_sync(0xFFFFFFFFu, t1, m);
        }
        float e0 = __expf(t0), e1 = __expf(t1);
        denom += e0 + e1;
        acc   += e0 * x0 + e1 * x1;
    }
    if (p < pend) {
        int s0 = g_csrc[p];
        float x0 = g_xl[(size_t)s0 * 128 + j];
        float v0 = x0 + xr_v; v0 = v0 > 0.f ? v0 : 0.2f * v0;
        float t0 = warp_sum(v0 * att_v);
        float e0 = __expf(t0);
        denom += e0;
        acc   += e0 * x0;
    }

    float o = fmaxf(acc / denom + bias[j], 0.f);
    int g = clampi(batch[d], 0, GMAX - 1);
    atomicMax((int*)&g_pooled[g * 128 + j], __float_as_int(o));
}

// ---------------------------------------------------------------------------
// Final MLP: out[g,:] = relu(pooled[g,:] @ W_mlp + b_mlp). One block per graph.
// ---------------------------------------------------------------------------
__global__ void __launch_bounds__(128) mlp_kernel(
    const float* __restrict__ W,
    const float* __restrict__ b,
    float* __restrict__ out)
{
    __shared__ float pbuf[128];
    int j = threadIdx.x, g = blockIdx.x;
    pbuf[j] = g_pooled[g * 128 + j];
    __syncthreads();
    float acc = b[j];
#pragma unroll 8
    for (int k = 0; k < 128; k++)
        acc += pbuf[k] * W[k * 128 + j];
    out[g * 128 + j] = fmaxf(acc, 0.f);
}

// ---------------------------------------------------------------------------
extern "C" void kernel_launch(void* const* d_in, const int* in_sizes, int n_in,
                              void* d_out, int out_size)
{
    const float* x     = (const float*)d_in[0];
    const int*   ei    = (const int*)d_in[1];
    const int*   batch = (const int*)d_in[2];
    int base = (n_in >= 10) ? 4 : 3;
    const float* Wl   = (const float*)d_in[base + 0];
    const float* Wr   = (const float*)d_in[base + 1];
    const float* att  = (const float*)d_in[base + 2];
    const float* bias = (const float*)d_in[base + 3];
    const float* Wm   = (const float*)d_in[base + 4];
    const float* bm   = (const float*)d_in[base + 5];

    int N = in_sizes[0] / 128;
    int E = in_sizes[1] / 2;
    int G = out_size / 128;
    float* out = (float*)d_out;
    int nb = (N + 1023) / 1024;

    init_kernel<<<(N + 255) / 256, 256>>>(N, G * 128);                 // 0
    hist_kernel<<<592, 256>>>(ei, E, N);                               // 1
    scan1_kernel<<<nb, 1024>>>(N);                                     // 2
    scan2_kernel<<<1, 64>>>(nb);                                       // 3
    scan3_kernel<<<nb, 1024>>>(N, E);                                  // 4

    dim3 ggrid(4, (N + 63) / 64);
    gemm_kernel<<<ggrid, 256>>>(x, Wl, Wr, N);                         // 5 (ncu target)

    fill_kernel<<<592, 256>>>(ei, E, N);                               // 6
    aggregate_kernel<<<N, 128>>>(att, bias, batch, N);                 // 7
    mlp_kernel<<<G, 128>>>(Wm, bm, out);                               // 8
}